// round 2
// baseline (speedup 1.0000x reference)
#include <cuda_runtime.h>
#include <cuda_bf16.h>
#include <mma.h>
#include <cstdint>

using namespace nvcuda;

// ---------------- problem constants ----------------
#define BATCH 8
#define CCH   320
#define DD    32
#define HH    32
#define WW_   16
#define LL    (DD*HH*WW_)          // 16384
#define HEADS 10
#define HDIM  32
#define NWIN  512                  // windows per sample
#define TOKENS (BATCH*LL)          // 131072

// ---------------- scratch (device globals; no mallocs allowed) ----------------
__device__ float g_t0 [(size_t)TOKENS * CCH];        // residual stream, (B*L, C)
__device__ float g_xw [(size_t)TOKENS * CCH];        // LN output (windowed order)
__device__ float g_qkv[(size_t)TOKENS * 3 * CCH];    // qkv (windowed order)
__device__ float g_att[(size_t)TOKENS * CCH];        // attention output (windowed order)
__device__ float g_mlp[(size_t)TOKENS * 4 * CCH];    // MLP hidden
__device__ int   g_map_ns[LL];                       // windowed idx -> spatial l (no shift)
__device__ int   g_map_s [LL];                       // windowed idx -> spatial l (shifted)

// ---------------- map init: window partition (+roll) as a permutation ----------------
__global__ void init_maps_kernel() {
    int i = blockIdx.x * blockDim.x + threadIdx.x;   // [0, 16384)
    if (i >= LL) return;
    int w = i >> 5, n = i & 31;
    int wd = w >> 6, wh = (w >> 3) & 7, ww = w & 7;  // window block coords (8,8,8)
    int zd = n >> 3, zh = (n >> 1) & 3, zw = n & 1;  // in-window coords (4,4,2)
    int dr = wd*4 + zd, hr = wh*4 + zh, wr = ww*2 + zw;  // rolled-space coords
    g_map_ns[i] = (dr*HH + hr)*WW_ + wr;
    int d0 = (dr + 2) & 31, h0 = (hr + 2) & 31, w0 = (wr + 1) & 15; // roll(-2,-2,-1)
    g_map_s[i]  = (d0*HH + h0)*WW_ + w0;
}

// ---------------- transpose (B,C,L) <-> (B*L, C) ----------------
__global__ void transpose_in_kernel(const float* __restrict__ x, float* __restrict__ t0) {
    __shared__ float tile[32][33];
    int b = blockIdx.z;
    int c0 = blockIdx.y * 32, l0 = blockIdx.x * 32;
    int tx = threadIdx.x, ty = threadIdx.y;
    tile[ty][tx] = x[((size_t)b*CCH + c0 + ty)*LL + l0 + tx];
    __syncthreads();
    t0[((size_t)b*LL + l0 + ty)*CCH + c0 + tx] = tile[tx][ty];
}

__global__ void transpose_out_kernel(const float* __restrict__ t0, float* __restrict__ out) {
    __shared__ float tile[32][33];
    int b = blockIdx.z;
    int c0 = blockIdx.y * 32, l0 = blockIdx.x * 32;
    int tx = threadIdx.x, ty = threadIdx.y;
    tile[ty][tx] = t0[((size_t)b*LL + l0 + ty)*CCH + c0 + tx];
    __syncthreads();
    out[((size_t)b*CCH + c0 + ty)*LL + l0 + tx] = tile[tx][ty];
}

// ---------------- LayerNorm (+ optional window-gather permutation) ----------------
// One warp per token. map==nullptr -> identity row order.
__global__ void ln_gather_kernel(const float* __restrict__ src, float* __restrict__ dst,
                                 const float* __restrict__ gma, const float* __restrict__ bta,
                                 const int* __restrict__ map) {
    int warp = (blockIdx.x * blockDim.x + threadIdx.x) >> 5;
    int lane = threadIdx.x & 31;
    if (warp >= TOKENS) return;
    size_t srow;
    if (map) {
        int bq = warp >> 14, i = warp & 16383;
        srow = ((size_t)bq << 14) + map[i];
    } else {
        srow = warp;
    }
    const float* xr = src + srow * CCH;
    float v[10];
    float s = 0.f;
#pragma unroll
    for (int j = 0; j < 10; j++) { v[j] = xr[lane + 32*j]; s += v[j]; }
#pragma unroll
    for (int o = 16; o; o >>= 1) s += __shfl_xor_sync(0xffffffffu, s, o);
    float mu = s * (1.f/320.f);
    float q = 0.f;
#pragma unroll
    for (int j = 0; j < 10; j++) { float d = v[j]-mu; q += d*d; }
#pragma unroll
    for (int o = 16; o; o >>= 1) q += __shfl_xor_sync(0xffffffffu, q, o);
    float rs = rsqrtf(q * (1.f/320.f) + 1e-5f);
    float* dr = dst + (size_t)warp * CCH;
#pragma unroll
    for (int j = 0; j < 10; j++) {
        int c = lane + 32*j;
        dr[c] = (v[j]-mu)*rs*gma[c] + bta[c];
    }
}

// ---------------- windowed attention ----------------
__device__ __forceinline__ int grp3(int p, int a, int b) { return p < a ? 0 : (p < b ? 1 : 2); }

__global__ void attn_kernel(const float* __restrict__ qkv, const float* __restrict__ btab,
                            float* __restrict__ out, int shifted) {
    int wg = blockIdx.x / HEADS;         // global window [0, 4096)
    int h  = blockIdx.x % HEADS;
    int n  = threadIdx.x >> 5;           // query token (warp = row)
    int m  = threadIdx.x & 31;           // key token / out channel
    __shared__ float sq[32][33], sk[32][33], sv[32][33];

    size_t rbase = (size_t)wg * 32;
    int col = h*HDIM + m;
    sq[n][m] = qkv[(rbase + n)*(3*CCH) + col];
    sk[n][m] = qkv[(rbase + n)*(3*CCH) + CCH + col];
    sv[n][m] = qkv[(rbase + n)*(3*CCH) + 2*CCH + col];
    __syncthreads();

    float s = 0.f;
#pragma unroll
    for (int d = 0; d < 32; d++) s += sq[n][d] * sk[m][d];
    s *= 0.17677669529663687f;           // 1/sqrt(32)

    int zdn = n >> 3, zhn = (n >> 1) & 3, zwn = n & 1;
    int zdm = m >> 3, zhm = (m >> 1) & 3, zwm = m & 1;
    int rel = ((zdn - zdm + 3)*7 + (zhn - zhm + 3))*3 + (zwn - zwm + 1);
    s += btab[rel*HEADS + h];

    if (shifted) {
        int wl = wg & (NWIN-1);
        int wd = wl >> 6, wh = (wl >> 3) & 7, ww = wl & 7;
        int gn = grp3(wd*4+zdn,28,30)*9 + grp3(wh*4+zhn,28,30)*3 + grp3(ww*2+zwn,14,15);
        int gm = grp3(wd*4+zdm,28,30)*9 + grp3(wh*4+zhm,28,30)*3 + grp3(ww*2+zwm,14,15);
        if (gn != gm) s -= 100.f;
    }

    // softmax over m (within warp)
    float mx = s;
#pragma unroll
    for (int o = 16; o; o >>= 1) mx = fmaxf(mx, __shfl_xor_sync(0xffffffffu, mx, o));
    float e = __expf(s - mx);
    float sum = e;
#pragma unroll
    for (int o = 16; o; o >>= 1) sum += __shfl_xor_sync(0xffffffffu, sum, o);
    float p = e / sum;

    __syncwarp();
    sq[n][m] = p;                        // reuse q smem for probabilities
    __syncwarp();

    float o = 0.f;
#pragma unroll
    for (int mm = 0; mm < 32; mm++) o += sq[n][mm] * sv[mm][m];
    out[(rbase + n)*CCH + h*HDIM + m] = o;
}

// ---------------- tf32 GEMM: C[M,N] = A[M,K] * B[K,N] (+ epilogue) ----------------
// EPI 0: out = acc + bias
// EPI 1: out = gelu(acc + bias)               (exact erf)
// EPI 2: resid[map-scattered row] += acc+bias (N == 320; window-reverse + residual)
// EPI 3: resid[row] += acc + bias             (N == 320)
// 64x64x32 tiles, 256 threads (8 warps, each 32x16), cp.async double-buffered.
// Static smem (<48KB) so no cudaFuncSetAttribute is needed.
#define GBM 64
#define GBN 64
#define GBK 32
#define SA_LD 36
#define SB_LD 68
#define SC_LD 68
#define SA_ELEMS (GBM*SA_LD)   // 2304
#define SB_ELEMS (GBK*SB_LD)   // 2176

__device__ __forceinline__ void cp_async16(void* sptr, const void* gptr) {
    uint32_t s = (uint32_t)__cvta_generic_to_shared(sptr);
    asm volatile("cp.async.cg.shared.global [%0], [%1], 16;\n" :: "r"(s), "l"(gptr));
}

typedef wmma::fragment<wmma::matrix_a, 16,16,8, wmma::precision::tf32, wmma::row_major> FragA;
typedef wmma::fragment<wmma::matrix_b, 16,16,8, wmma::precision::tf32, wmma::row_major> FragB;
typedef wmma::fragment<wmma::accumulator, 16,16,8, float> FragC;

template<int EPI>
__global__ void __launch_bounds__(256)
gemm_tf32_kernel(const float* __restrict__ A, const float* __restrict__ B,
                 const float* __restrict__ bias, float* __restrict__ C,
                 const int* __restrict__ map, int K, int N) {
    __shared__ float sA[2][SA_ELEMS];
    __shared__ float sB[2][SB_ELEMS];

    const int tid = threadIdx.x;
    const int bm = blockIdx.y, bn = blockIdx.x;
    const int KT = K >> 5;
    const float* Abase = A + (size_t)bm * GBM * K;
    const float* Bbase = B + (size_t)bn * GBN;

    const int warp = tid >> 5;
    const int wm = warp & 1;             // 2 row-groups of 32
    const int wn = warp >> 1;            // 4 col-groups of 16

    FragC acc[2];
#pragma unroll
    for (int i = 0; i < 2; i++) wmma::fill_fragment(acc[i], 0.f);

    auto load_tile = [&](int kt, int buf) {
        float* a = sA[buf];
#pragma unroll
        for (int i = 0; i < 2; i++) {
            int idx = tid + i*256;           // [0,512): 64 rows x 8 float4
            int r = idx >> 3, c4 = (idx & 7) << 2;
            cp_async16(a + r*SA_LD + c4, Abase + (size_t)r*K + kt*GBK + c4);
        }
        float* b = sB[buf];
#pragma unroll
        for (int i = 0; i < 2; i++) {
            int idx = tid + i*256;           // [0,512): 32 rows x 16 float4
            int r = idx >> 4, c4 = (idx & 15) << 2;
            cp_async16(b + r*SB_LD + c4, Bbase + (size_t)(kt*GBK + r)*N + c4);
        }
        asm volatile("cp.async.commit_group;\n" ::);
    };

    load_tile(0, 0);
    for (int kt = 0; kt < KT; kt++) {
        if (kt + 1 < KT) {
            load_tile(kt + 1, (kt + 1) & 1);
            asm volatile("cp.async.wait_group 1;\n" ::);
        } else {
            asm volatile("cp.async.wait_group 0;\n" ::);
        }
        __syncthreads();
        const float* a = sA[kt & 1];
        const float* b = sB[kt & 1];
#pragma unroll
        for (int ks = 0; ks < 4; ks++) {
            FragA af[2]; FragB bf;
#pragma unroll
            for (int i = 0; i < 2; i++) {
                wmma::load_matrix_sync(af[i], a + (wm*32 + i*16)*SA_LD + ks*8, SA_LD);
#pragma unroll
                for (int t = 0; t < af[i].num_elements; t++)
                    af[i].x[t] = wmma::__float_to_tf32(af[i].x[t]);
            }
            wmma::load_matrix_sync(bf, b + (ks*8)*SB_LD + wn*16, SB_LD);
#pragma unroll
            for (int t = 0; t < bf.num_elements; t++)
                bf.x[t] = wmma::__float_to_tf32(bf.x[t]);
#pragma unroll
            for (int i = 0; i < 2; i++)
                wmma::mma_sync(acc[i], af[i], bf, acc[i]);
        }
        __syncthreads();
    }

    // stage accumulators to smem (alias sA+sB region is too small: use sA both buffers = 4608 floats;
    // need 64*68 = 4352 floats -> fits in sA alone)
    float* sC = &sA[0][0];
#pragma unroll
    for (int i = 0; i < 2; i++)
        wmma::store_matrix_sync(sC + (wm*32 + i*16)*SC_LD + wn*16, acc[i], SC_LD, wmma::mem_row_major);
    __syncthreads();

#pragma unroll 4
    for (int idx = tid; idx < GBM*GBN; idx += 256) {
        int r = idx >> 6, c = idx & 63;
        int col = bn*GBN + c;
        float v = sC[r*SC_LD + c] + __ldg(&bias[col]);
        size_t row = (size_t)bm*GBM + r;
        if (EPI == 0) {
            C[row*N + col] = v;
        } else if (EPI == 1) {
            C[row*N + col] = 0.5f*v*(1.f + erff(v*0.70710678118654752f));
        } else if (EPI == 2) {
            int bq = (int)(row >> 14);
            int l  = map[row & 16383];
            C[(((size_t)bq << 14) + l)*CCH + col] += v;
        } else { // EPI == 3
            C[row*CCH + col] += v;
        }
    }
}

// ---------------- host orchestration ----------------
static void run_block(const float* const* P, int* map, int shifted,
                      float* t0, float* xw, float* qkv, float* att, float* mlp) {
    // P: ln1g ln1b qkvw qkvb bias projw projb ln2g ln2b f1w f1b f2w f2b
    ln_gather_kernel<<<TOKENS/8, 256>>>(t0, xw, P[0], P[1], map);
    gemm_tf32_kernel<0><<<dim3(3*CCH/GBN, TOKENS/GBM), 256>>>(
        xw, P[2], P[3], qkv, nullptr, CCH, 3*CCH);
    attn_kernel<<<BATCH*NWIN*HEADS, 1024>>>(qkv, P[4], att, shifted);
    gemm_tf32_kernel<2><<<dim3(CCH/GBN, TOKENS/GBM), 256>>>(
        att, P[5], P[6], t0, map, CCH, CCH);
    ln_gather_kernel<<<TOKENS/8, 256>>>(t0, xw, P[7], P[8], nullptr);
    gemm_tf32_kernel<1><<<dim3(4*CCH/GBN, TOKENS/GBM), 256>>>(
        xw, P[9], P[10], mlp, nullptr, CCH, 4*CCH);
    gemm_tf32_kernel<3><<<dim3(CCH/GBN, TOKENS/GBM), 256>>>(
        mlp, P[11], P[12], t0, nullptr, 4*CCH, CCH);
}

extern "C" void kernel_launch(void* const* d_in, const int* in_sizes, int n_in,
                              void* d_out, int out_size) {
    (void)in_sizes; (void)n_in; (void)out_size;
    const float* x = (const float*)d_in[0];
    const float* P1[13];
    const float* P2[13];
    for (int i = 0; i < 13; i++) P1[i] = (const float*)d_in[1 + i];
    for (int i = 0; i < 13; i++) P2[i] = (const float*)d_in[14 + i];

    float *t0, *xw, *qkv, *att, *mlp;
    int *map_ns, *map_s;
    cudaGetSymbolAddress((void**)&t0,  g_t0);
    cudaGetSymbolAddress((void**)&xw,  g_xw);
    cudaGetSymbolAddress((void**)&qkv, g_qkv);
    cudaGetSymbolAddress((void**)&att, g_att);
    cudaGetSymbolAddress((void**)&mlp, g_mlp);
    cudaGetSymbolAddress((void**)&map_ns, g_map_ns);
    cudaGetSymbolAddress((void**)&map_s,  g_map_s);

    init_maps_kernel<<<LL/256, 256>>>();
    transpose_in_kernel<<<dim3(LL/32, CCH/32, BATCH), dim3(32,32)>>>(x, t0);
    run_block(P1, map_ns, 0, t0, xw, qkv, att, mlp);
    run_block(P2, map_s,  1, t0, xw, qkv, att, mlp);
    transpose_out_kernel<<<dim3(LL/32, CCH/32, BATCH), dim3(32,32)>>>(t0, (float*)d_out);
}

// round 5
// speedup vs baseline: 2.8106x; 2.8106x over previous
#include <cuda_runtime.h>
#include <cuda_fp16.h>
#include <mma.h>
#include <cstdint>

using namespace nvcuda;

// ---------------- problem constants ----------------
#define BATCH 8
#define CCH   320
#define DD    32
#define HH    32
#define WW_   16
#define LL    (DD*HH*WW_)          // 16384
#define HEADS 10
#define HDIM  32
#define NWIN  512                  // windows per sample
#define TOKENS (BATCH*LL)          // 131072

// ---------------- scratch (device globals; no mallocs allowed) ----------------
__device__ float  g_t0 [(size_t)TOKENS * CCH];        // residual stream fp32, (B*L, C)
__device__ __half g_xw [(size_t)TOKENS * CCH];        // LN output fp16 (windowed order)
__device__ __half g_qkv[(size_t)TOKENS * 3 * CCH];    // qkv fp16 (windowed order)
__device__ __half g_att[(size_t)TOKENS * CCH];        // attention output fp16
__device__ __half g_mlp[(size_t)TOKENS * 4 * CCH];    // MLP hidden fp16
__device__ int    g_map_ns[LL];                       // windowed idx -> spatial l (no shift)
__device__ int    g_map_s [LL];                       // windowed idx -> spatial l (shifted)
// fp16 weight copies (converted once per call)
__device__ __half g_wqkv[2][CCH*3*CCH];
__device__ __half g_wproj[2][CCH*CCH];
__device__ __half g_wf1 [2][CCH*4*CCH];
__device__ __half g_wf2 [2][4*CCH*CCH];

// ---------------- fp32 -> fp16 weight cast ----------------
__global__ void f2h_kernel(const float* __restrict__ src, __half* __restrict__ dst, int n) {
    int i = blockIdx.x * blockDim.x + threadIdx.x;
    if (i < n) dst[i] = __float2half_rn(src[i]);
}

// ---------------- map init: window partition (+roll) as a permutation ----------------
__global__ void init_maps_kernel() {
    int i = blockIdx.x * blockDim.x + threadIdx.x;   // [0, 16384)
    if (i >= LL) return;
    int w = i >> 5, n = i & 31;
    int wd = w >> 6, wh = (w >> 3) & 7, ww = w & 7;  // window block coords (8,8,8)
    int zd = n >> 3, zh = (n >> 1) & 3, zw = n & 1;  // in-window coords (4,4,2)
    int dr = wd*4 + zd, hr = wh*4 + zh, wr = ww*2 + zw;
    g_map_ns[i] = (dr*HH + hr)*WW_ + wr;
    int d0 = (dr + 2) & 31, h0 = (hr + 2) & 31, w0 = (wr + 1) & 15; // roll(-2,-2,-1)
    g_map_s[i]  = (d0*HH + h0)*WW_ + w0;
}

// ---------------- transpose (B,C,L) <-> (B*L, C) ----------------
__global__ void transpose_in_kernel(const float* __restrict__ x, float* __restrict__ t0) {
    __shared__ float tile[32][33];
    int b = blockIdx.z;
    int c0 = blockIdx.y * 32, l0 = blockIdx.x * 32;
    int tx = threadIdx.x, ty = threadIdx.y;
    tile[ty][tx] = x[((size_t)b*CCH + c0 + ty)*LL + l0 + tx];
    __syncthreads();
    t0[((size_t)b*LL + l0 + ty)*CCH + c0 + tx] = tile[tx][ty];
}

__global__ void transpose_out_kernel(const float* __restrict__ t0, float* __restrict__ out) {
    __shared__ float tile[32][33];
    int b = blockIdx.z;
    int c0 = blockIdx.y * 32, l0 = blockIdx.x * 32;
    int tx = threadIdx.x, ty = threadIdx.y;
    tile[ty][tx] = t0[((size_t)b*LL + l0 + ty)*CCH + c0 + tx];
    __syncthreads();
    out[((size_t)b*CCH + c0 + ty)*LL + l0 + tx] = tile[tx][ty];
}

// ---------------- LayerNorm (+ optional window-gather), fp32 in -> fp16 out ----------------
// One warp per token; float4 vector loads. 320 floats = 80 float4: lanes 0..31 read
// float4 #lane and #(lane+32); tail 16 float4 (indices 64..79) are split so each lane
// handles 2 scalars: lanes 0..15 take .x/.y of float4 #(64+lane), lanes 16..31 take
// .z/.w of float4 #(64+lane-16). Every column covered exactly once.
__global__ void ln_gather_kernel(const float* __restrict__ src, __half* __restrict__ dst,
                                 const float* __restrict__ gma, const float* __restrict__ bta,
                                 const int* __restrict__ map) {
    int warp = (blockIdx.x * blockDim.x + threadIdx.x) >> 5;
    int lane = threadIdx.x & 31;
    if (warp >= TOKENS) return;
    size_t srow;
    if (map) {
        int bq = warp >> 14, i = warp & 16383;
        srow = ((size_t)bq << 14) + map[i];
    } else {
        srow = warp;
    }
    const float*  xr  = src + srow * CCH;
    const float4* xr4 = (const float4*)xr;
    float v[10];
    float4 a0 = xr4[lane];
    float4 a1 = xr4[lane + 32];
    v[0]=a0.x; v[1]=a0.y; v[2]=a0.z; v[3]=a0.w;
    v[4]=a1.x; v[5]=a1.y; v[6]=a1.z; v[7]=a1.w;
    int cols[10];
    cols[0]=lane*4+0; cols[1]=lane*4+1; cols[2]=lane*4+2; cols[3]=lane*4+3;
    cols[4]=128+lane*4+0; cols[5]=128+lane*4+1; cols[6]=128+lane*4+2; cols[7]=128+lane*4+3;
    if (lane < 16) { cols[8]=256+lane*4+0;      cols[9]=256+lane*4+1; }
    else           { cols[8]=256+(lane-16)*4+2; cols[9]=256+(lane-16)*4+3; }
    v[8] = xr[cols[8]];
    v[9] = xr[cols[9]];

    float s = 0.f;
#pragma unroll
    for (int j = 0; j < 10; j++) s += v[j];
#pragma unroll
    for (int o = 16; o; o >>= 1) s += __shfl_xor_sync(0xffffffffu, s, o);
    float mu = s * (1.f/320.f);
    float q = 0.f;
#pragma unroll
    for (int j = 0; j < 10; j++) { float d = v[j]-mu; q += d*d; }
#pragma unroll
    for (int o = 16; o; o >>= 1) q += __shfl_xor_sync(0xffffffffu, q, o);
    float rs = rsqrtf(q * (1.f/320.f) + 1e-5f);
    __half* dr = dst + (size_t)warp * CCH;
#pragma unroll
    for (int j = 0; j < 10; j++) {
        int c = cols[j];
        dr[c] = __float2half_rn((v[j]-mu)*rs*gma[c] + bta[c]);
    }
}

// ---------------- windowed attention (fp16 I/O, fp32 math) ----------------
__device__ __forceinline__ int grp3(int p, int a, int b) { return p < a ? 0 : (p < b ? 1 : 2); }

__global__ void attn_kernel(const __half* __restrict__ qkv, const float* __restrict__ btab,
                            __half* __restrict__ out, int shifted) {
    int wg = blockIdx.x / HEADS;         // global window [0, 4096)
    int h  = blockIdx.x % HEADS;
    int n  = threadIdx.x >> 5;           // query token (warp = row)
    int m  = threadIdx.x & 31;           // key token / out channel
    __shared__ float sq[32][33], sk[32][33], sv[32][33];

    size_t rbase = (size_t)wg * 32;
    int col = h*HDIM + m;
    sq[n][m] = __half2float(qkv[(rbase + n)*(3*CCH) + col]);
    sk[n][m] = __half2float(qkv[(rbase + n)*(3*CCH) + CCH + col]);
    sv[n][m] = __half2float(qkv[(rbase + n)*(3*CCH) + 2*CCH + col]);
    __syncthreads();

    float s = 0.f;
#pragma unroll
    for (int d = 0; d < 32; d++) s += sq[n][d] * sk[m][d];
    s *= 0.17677669529663687f;           // 1/sqrt(32)

    int zdn = n >> 3, zhn = (n >> 1) & 3, zwn = n & 1;
    int zdm = m >> 3, zhm = (m >> 1) & 3, zwm = m & 1;
    int rel = ((zdn - zdm + 3)*7 + (zhn - zhm + 3))*3 + (zwn - zwm + 1);
    s += btab[rel*HEADS + h];

    if (shifted) {
        int wl = wg & (NWIN-1);
        int wd = wl >> 6, wh = (wl >> 3) & 7, ww = wl & 7;
        int gn = grp3(wd*4+zdn,28,30)*9 + grp3(wh*4+zhn,28,30)*3 + grp3(ww*2+zwn,14,15);
        int gm = grp3(wd*4+zdm,28,30)*9 + grp3(wh*4+zhm,28,30)*3 + grp3(ww*2+zwm,14,15);
        if (gn != gm) s -= 100.f;
    }

    float mx = s;
#pragma unroll
    for (int o = 16; o; o >>= 1) mx = fmaxf(mx, __shfl_xor_sync(0xffffffffu, mx, o));
    float e = __expf(s - mx);
    float sum = e;
#pragma unroll
    for (int o = 16; o; o >>= 1) sum += __shfl_xor_sync(0xffffffffu, sum, o);
    float p = e / sum;

    __syncwarp();
    sq[n][m] = p;
    __syncwarp();

    float o = 0.f;
#pragma unroll
    for (int mm = 0; mm < 32; mm++) o += sq[n][mm] * sv[mm][m];
    out[(rbase + n)*CCH + h*HDIM + m] = __float2half_rn(o);
}

// ---------------- fp16 GEMM: C[M,N] = A[M,K]*B[K,N] (+ fused epilogue) ----------------
// EPI 0: qkv  = half(acc + bias)
// EPI 1: mlp  = half(gelu(acc + bias))          (exact erf)
// EPI 2: t0[map-scattered row] += acc + bias    (window-reverse + residual, fp32)
// EPI 3: t0[row] += acc + bias                  (fp32)
// 128x64x32 tile, 256 threads = 8 warps (4x2), each warp 32x32 via 2x2 m16n16k16.
#define GBM 128
#define GBN 64
#define GBK 32
#define SA_LD 40            // halves
#define SB_LD 72            // halves
#define SC_LD 68            // floats
#define SA_BYTES (GBM*SA_LD*2)      // 10240
#define SB_BYTES (GBK*SB_LD*2)      // 4608
#define SMEM_BYTES (GBM*SC_LD*4)    // 34816 > 2*(SA+SB)=29696

__device__ __forceinline__ void cp_async16(void* sptr, const void* gptr) {
    uint32_t s = (uint32_t)__cvta_generic_to_shared(sptr);
    asm volatile("cp.async.cg.shared.global [%0], [%1], 16;\n" :: "r"(s), "l"(gptr));
}

typedef wmma::fragment<wmma::matrix_a, 16,16,16, __half, wmma::row_major> FragA;
typedef wmma::fragment<wmma::matrix_b, 16,16,16, __half, wmma::row_major> FragB;
typedef wmma::fragment<wmma::accumulator, 16,16,16, float> FragC;

template<int EPI>
__global__ void __launch_bounds__(256)
gemm_f16_kernel(const __half* __restrict__ A, const __half* __restrict__ B,
                const float* __restrict__ bias, void* __restrict__ Cv,
                const int* __restrict__ map, int K, int N) {
    __shared__ __align__(16) char smem[SMEM_BYTES];
    __half* sA0 = (__half*)smem;                         // [2][128*40]
    __half* sB0 = (__half*)(smem + 2*SA_BYTES);          // [2][32*72]
    float*  sC  = (float*)smem;                          // [128][68] epilogue alias

    const int tid = threadIdx.x;
    const int bm = blockIdx.y, bn = blockIdx.x;
    const int KT = K >> 5;
    const __half* Abase = A + (size_t)bm * GBM * K;
    const __half* Bbase = B + (size_t)bn * GBN;

    const int warp = tid >> 5;
    const int wm = warp & 3;             // 4 row-groups of 32
    const int wn = warp >> 2;            // 2 col-groups of 32

    FragC acc[2][2];
#pragma unroll
    for (int i = 0; i < 2; i++)
#pragma unroll
        for (int j = 0; j < 2; j++) wmma::fill_fragment(acc[i][j], 0.f);

    auto load_tile = [&](int kt, int buf) {
        __half* a = sA0 + buf*(GBM*SA_LD);
#pragma unroll
        for (int i = 0; i < 2; i++) {
            int idx = tid + i*256;           // [0,512): 128 rows x 4 chunks of 8 halves
            int r = idx >> 2, c8 = (idx & 3) << 3;
            cp_async16(a + r*SA_LD + c8, Abase + (size_t)r*K + kt*GBK + c8);
        }
        __half* b = sB0 + buf*(GBK*SB_LD);
        {
            int idx = tid;                   // [0,256): 32 rows x 8 chunks of 8 halves
            int r = idx >> 3, c8 = (idx & 7) << 3;
            cp_async16(b + r*SB_LD + c8, Bbase + (size_t)(kt*GBK + r)*N + c8);
        }
        asm volatile("cp.async.commit_group;\n" ::);
    };

    load_tile(0, 0);
    for (int kt = 0; kt < KT; kt++) {
        if (kt + 1 < KT) {
            load_tile(kt + 1, (kt + 1) & 1);
            asm volatile("cp.async.wait_group 1;\n" ::);
        } else {
            asm volatile("cp.async.wait_group 0;\n" ::);
        }
        __syncthreads();
        const __half* a = sA0 + (kt & 1)*(GBM*SA_LD);
        const __half* b = sB0 + (kt & 1)*(GBK*SB_LD);
#pragma unroll
        for (int ks = 0; ks < 2; ks++) {     // two K=16 steps per 32-tile
            FragA af[2]; FragB bf[2];
#pragma unroll
            for (int i = 0; i < 2; i++)
                wmma::load_matrix_sync(af[i], a + (wm*32 + i*16)*SA_LD + ks*16, SA_LD);
#pragma unroll
            for (int j = 0; j < 2; j++)
                wmma::load_matrix_sync(bf[j], b + (ks*16)*SB_LD + wn*32 + j*16, SB_LD);
#pragma unroll
            for (int i = 0; i < 2; i++)
#pragma unroll
                for (int j = 0; j < 2; j++)
                    wmma::mma_sync(acc[i][j], af[i], bf[j], acc[i][j]);
        }
        __syncthreads();
    }

    // stage accumulators to smem fp32, then coalesced fused epilogue
#pragma unroll
    for (int i = 0; i < 2; i++)
#pragma unroll
        for (int j = 0; j < 2; j++)
            wmma::store_matrix_sync(sC + (wm*32 + i*16)*SC_LD + wn*32 + j*16,
                                    acc[i][j], SC_LD, wmma::mem_row_major);
    __syncthreads();

#pragma unroll 4
    for (int idx = tid; idx < GBM*GBN; idx += 256) {
        int r = idx >> 6, c = idx & 63;
        int col = bn*GBN + c;
        float v = sC[r*SC_LD + c] + __ldg(&bias[col]);
        size_t row = (size_t)bm*GBM + r;
        if (EPI == 0) {
            ((__half*)Cv)[row*N + col] = __float2half_rn(v);
        } else if (EPI == 1) {
            ((__half*)Cv)[row*N + col] = __float2half_rn(0.5f*v*(1.f + erff(v*0.70710678118654752f)));
        } else if (EPI == 2) {
            int bq = (int)(row >> 14);
            int l  = map[row & 16383];
            ((float*)Cv)[(((size_t)bq << 14) + l)*CCH + col] += v;
        } else { // EPI == 3
            ((float*)Cv)[row*CCH + col] += v;
        }
    }
}

// ---------------- host orchestration ----------------
static void run_block(const float* const* P, const __half* wqkv, const __half* wproj,
                      const __half* wf1, const __half* wf2, int* map, int shifted,
                      float* t0, __half* xw, __half* qkv, __half* att, __half* mlp) {
    // P: ln1g ln1b qkvw qkvb bias projw projb ln2g ln2b f1w f1b f2w f2b
    ln_gather_kernel<<<TOKENS/8, 256>>>(t0, xw, P[0], P[1], map);
    gemm_f16_kernel<0><<<dim3(3*CCH/GBN, TOKENS/GBM), 256>>>(
        xw, wqkv, P[3], qkv, nullptr, CCH, 3*CCH);
    attn_kernel<<<BATCH*NWIN*HEADS, 1024>>>(qkv, P[4], att, shifted);
    gemm_f16_kernel<2><<<dim3(CCH/GBN, TOKENS/GBM), 256>>>(
        att, wproj, P[6], t0, map, CCH, CCH);
    ln_gather_kernel<<<TOKENS/8, 256>>>(t0, xw, P[7], P[8], nullptr);
    gemm_f16_kernel<1><<<dim3(4*CCH/GBN, TOKENS/GBM), 256>>>(
        xw, wf1, P[10], mlp, nullptr, CCH, 4*CCH);
    gemm_f16_kernel<3><<<dim3(CCH/GBN, TOKENS/GBM), 256>>>(
        mlp, wf2, P[12], t0, nullptr, 4*CCH, CCH);
}

extern "C" void kernel_launch(void* const* d_in, const int* in_sizes, int n_in,
                              void* d_out, int out_size) {
    (void)in_sizes; (void)n_in; (void)out_size;
    const float* x = (const float*)d_in[0];
    const float* P1[13];
    const float* P2[13];
    for (int i = 0; i < 13; i++) P1[i] = (const float*)d_in[1 + i];
    for (int i = 0; i < 13; i++) P2[i] = (const float*)d_in[14 + i];

    float *t0; __half *xw, *qkv, *att, *mlp;
    __half *wqkv, *wproj, *wf1, *wf2;
    int *map_ns, *map_s;
    cudaGetSymbolAddress((void**)&t0,  g_t0);
    cudaGetSymbolAddress((void**)&xw,  g_xw);
    cudaGetSymbolAddress((void**)&qkv, g_qkv);
    cudaGetSymbolAddress((void**)&att, g_att);
    cudaGetSymbolAddress((void**)&mlp, g_mlp);
    cudaGetSymbolAddress((void**)&wqkv, g_wqkv);
    cudaGetSymbolAddress((void**)&wproj, g_wproj);
    cudaGetSymbolAddress((void**)&wf1, g_wf1);
    cudaGetSymbolAddress((void**)&wf2, g_wf2);
    cudaGetSymbolAddress((void**)&map_ns, g_map_ns);
    cudaGetSymbolAddress((void**)&map_s,  g_map_s);

    // cast all weights to fp16 (both blocks)
    const int NW1 = CCH*3*CCH, NW2 = CCH*CCH, NW3 = CCH*4*CCH;
    for (int blk = 0; blk < 2; blk++) {
        const float* const* P = blk ? P2 : P1;
        f2h_kernel<<<(NW1+255)/256, 256>>>(P[2],  wqkv  + (size_t)blk*NW1, NW1);
        f2h_kernel<<<(NW2+255)/256, 256>>>(P[5],  wproj + (size_t)blk*NW2, NW2);
        f2h_kernel<<<(NW3+255)/256, 256>>>(P[9],  wf1   + (size_t)blk*NW3, NW3);
        f2h_kernel<<<(NW3+255)/256, 256>>>(P[11], wf2   + (size_t)blk*NW3, NW3);
    }

    init_maps_kernel<<<LL/256, 256>>>();
    transpose_in_kernel<<<dim3(LL/32, CCH/32, BATCH), dim3(32,32)>>>(x, t0);
    run_block(P1, wqkv,         wproj,         wf1,         wf2,         map_ns, 0, t0, xw, qkv, att, mlp);
    run_block(P2, wqkv + NW1,   wproj + NW2,   wf1 + NW3,   wf2 + NW3,   map_s,  1, t0, xw, qkv, att, mlp);
    transpose_out_kernel<<<dim3(LL/32, CCH/32, BATCH), dim3(32,32)>>>(t0, (float*)d_out);
}

// round 7
// speedup vs baseline: 2.9225x; 1.0398x over previous
#include <cuda_runtime.h>
#include <cuda_fp16.h>
#include <mma.h>
#include <cstdint>

using namespace nvcuda;

// ---------------- problem constants ----------------
#define BATCH 8
#define CCH   320
#define DD    32
#define HH    32
#define WW_   16
#define LL    (DD*HH*WW_)          // 16384
#define HEADS 10
#define HDIM  32
#define NWIN  512                  // windows per sample
#define TOKENS (BATCH*LL)          // 131072

// ---------------- scratch (device globals; no mallocs allowed) ----------------
__device__ float  g_t0 [(size_t)TOKENS * CCH];        // residual stream fp32, (B*L, C)
__device__ __half g_xw [(size_t)TOKENS * CCH];        // LN output fp16 (windowed order)
__device__ __half g_qkv[(size_t)TOKENS * 3 * CCH];    // qkv fp16 (windowed order)
__device__ __half g_att[(size_t)TOKENS * CCH];        // attention output fp16
__device__ __half g_mlp[(size_t)TOKENS * 4 * CCH];    // MLP hidden fp16
__device__ int    g_map_ns[LL];                       // windowed idx -> spatial l (no shift)
__device__ int    g_map_s [LL];                       // windowed idx -> spatial l (shifted)
// fp16 weight copies (converted once per call)
__device__ __half g_wqkv[2][CCH*3*CCH];
__device__ __half g_wproj[2][CCH*CCH];
__device__ __half g_wf1 [2][CCH*4*CCH];
__device__ __half g_wf2 [2][4*CCH*CCH];

// ---------------- fp32 -> fp16 weight cast ----------------
__global__ void f2h_kernel(const float* __restrict__ src, __half* __restrict__ dst, int n) {
    int i = blockIdx.x * blockDim.x + threadIdx.x;
    if (i < n) dst[i] = __float2half_rn(src[i]);
}

// ---------------- map init: window partition (+roll) as a permutation ----------------
__global__ void init_maps_kernel() {
    int i = blockIdx.x * blockDim.x + threadIdx.x;   // [0, 16384)
    if (i >= LL) return;
    int w = i >> 5, n = i & 31;
    int wd = w >> 6, wh = (w >> 3) & 7, ww = w & 7;  // window block coords (8,8,8)
    int zd = n >> 3, zh = (n >> 1) & 3, zw = n & 1;  // in-window coords (4,4,2)
    int dr = wd*4 + zd, hr = wh*4 + zh, wr = ww*2 + zw;
    g_map_ns[i] = (dr*HH + hr)*WW_ + wr;
    int d0 = (dr + 2) & 31, h0 = (hr + 2) & 31, w0 = (wr + 1) & 15; // roll(-2,-2,-1)
    g_map_s[i]  = (d0*HH + h0)*WW_ + w0;
}

// ---------------- transpose (B,C,L) <-> (B*L, C) ----------------
__global__ void transpose_in_kernel(const float* __restrict__ x, float* __restrict__ t0) {
    __shared__ float tile[32][33];
    int b = blockIdx.z;
    int c0 = blockIdx.y * 32, l0 = blockIdx.x * 32;
    int tx = threadIdx.x, ty = threadIdx.y;
    tile[ty][tx] = x[((size_t)b*CCH + c0 + ty)*LL + l0 + tx];
    __syncthreads();
    t0[((size_t)b*LL + l0 + ty)*CCH + c0 + tx] = tile[tx][ty];
}

__global__ void transpose_out_kernel(const float* __restrict__ t0, float* __restrict__ out) {
    __shared__ float tile[32][33];
    int b = blockIdx.z;
    int c0 = blockIdx.y * 32, l0 = blockIdx.x * 32;
    int tx = threadIdx.x, ty = threadIdx.y;
    tile[ty][tx] = t0[((size_t)b*LL + l0 + ty)*CCH + c0 + tx];
    __syncthreads();
    out[((size_t)b*CCH + c0 + ty)*LL + l0 + tx] = tile[tx][ty];
}

// ---------------- LayerNorm (+ optional window-gather), fp32 in -> fp16 out ----------------
__global__ void ln_gather_kernel(const float* __restrict__ src, __half* __restrict__ dst,
                                 const float* __restrict__ gma, const float* __restrict__ bta,
                                 const int* __restrict__ map) {
    int warp = (blockIdx.x * blockDim.x + threadIdx.x) >> 5;
    int lane = threadIdx.x & 31;
    if (warp >= TOKENS) return;
    size_t srow;
    if (map) {
        int bq = warp >> 14, i = warp & 16383;
        srow = ((size_t)bq << 14) + map[i];
    } else {
        srow = warp;
    }
    const float*  xr  = src + srow * CCH;
    const float4* xr4 = (const float4*)xr;
    float v[10];
    float4 a0 = xr4[lane];
    float4 a1 = xr4[lane + 32];
    v[0]=a0.x; v[1]=a0.y; v[2]=a0.z; v[3]=a0.w;
    v[4]=a1.x; v[5]=a1.y; v[6]=a1.z; v[7]=a1.w;
    int cols[10];
    cols[0]=lane*4+0; cols[1]=lane*4+1; cols[2]=lane*4+2; cols[3]=lane*4+3;
    cols[4]=128+lane*4+0; cols[5]=128+lane*4+1; cols[6]=128+lane*4+2; cols[7]=128+lane*4+3;
    if (lane < 16) { cols[8]=256+lane*4+0;      cols[9]=256+lane*4+1; }
    else           { cols[8]=256+(lane-16)*4+2; cols[9]=256+(lane-16)*4+3; }
    v[8] = xr[cols[8]];
    v[9] = xr[cols[9]];

    float s = 0.f;
#pragma unroll
    for (int j = 0; j < 10; j++) s += v[j];
#pragma unroll
    for (int o = 16; o; o >>= 1) s += __shfl_xor_sync(0xffffffffu, s, o);
    float mu = s * (1.f/320.f);
    float q = 0.f;
#pragma unroll
    for (int j = 0; j < 10; j++) { float d = v[j]-mu; q += d*d; }
#pragma unroll
    for (int o = 16; o; o >>= 1) q += __shfl_xor_sync(0xffffffffu, q, o);
    float rs = rsqrtf(q * (1.f/320.f) + 1e-5f);
    __half* dr = dst + (size_t)warp * CCH;
    __half h[10];
#pragma unroll
    for (int j = 0; j < 10; j++) {
        int c = cols[j];
        h[j] = __float2half_rn((v[j]-mu)*rs*gma[c] + bta[c]);
    }
    *(__half2*)&dr[cols[0]] = __halves2half2(h[0], h[1]);
    *(__half2*)&dr[cols[2]] = __halves2half2(h[2], h[3]);
    *(__half2*)&dr[cols[4]] = __halves2half2(h[4], h[5]);
    *(__half2*)&dr[cols[6]] = __halves2half2(h[6], h[7]);
    *(__half2*)&dr[cols[8]] = __halves2half2(h[8], h[9]);
}

// ---------------- windowed attention (fp16 I/O, fp32 math) ----------------
__device__ __forceinline__ int grp3(int p, int a, int b) { return p < a ? 0 : (p < b ? 1 : 2); }

__global__ void attn_kernel(const __half* __restrict__ qkv, const float* __restrict__ btab,
                            __half* __restrict__ out, int shifted) {
    int wg = blockIdx.x / HEADS;         // global window [0, 4096)
    int h  = blockIdx.x % HEADS;
    int n  = threadIdx.x >> 5;           // query token (warp = row)
    int m  = threadIdx.x & 31;           // key token / out channel
    __shared__ float sq[32][33], sk[32][33], sv[32][33];

    size_t rbase = (size_t)wg * 32;
    int col = h*HDIM + m;
    sq[n][m] = __half2float(qkv[(rbase + n)*(3*CCH) + col]);
    sk[n][m] = __half2float(qkv[(rbase + n)*(3*CCH) + CCH + col]);
    sv[n][m] = __half2float(qkv[(rbase + n)*(3*CCH) + 2*CCH + col]);
    __syncthreads();

    float s = 0.f;
#pragma unroll
    for (int d = 0; d < 32; d++) s += sq[n][d] * sk[m][d];
    s *= 0.17677669529663687f;           // 1/sqrt(32)

    int zdn = n >> 3, zhn = (n >> 1) & 3, zwn = n & 1;
    int zdm = m >> 3, zhm = (m >> 1) & 3, zwm = m & 1;
    int rel = ((zdn - zdm + 3)*7 + (zhn - zhm + 3))*3 + (zwn - zwm + 1);
    s += btab[rel*HEADS + h];

    if (shifted) {
        int wl = wg & (NWIN-1);
        int wd = wl >> 6, wh = (wl >> 3) & 7, ww = wl & 7;
        int gn = grp3(wd*4+zdn,28,30)*9 + grp3(wh*4+zhn,28,30)*3 + grp3(ww*2+zwn,14,15);
        int gm = grp3(wd*4+zdm,28,30)*9 + grp3(wh*4+zhm,28,30)*3 + grp3(ww*2+zwm,14,15);
        if (gn != gm) s -= 100.f;
    }

    float mx = s;
#pragma unroll
    for (int o = 16; o; o >>= 1) mx = fmaxf(mx, __shfl_xor_sync(0xffffffffu, mx, o));
    float e = __expf(s - mx);
    float sum = e;
#pragma unroll
    for (int o = 16; o; o >>= 1) sum += __shfl_xor_sync(0xffffffffu, sum, o);
    float p = e / sum;

    __syncwarp();
    sq[n][m] = p;
    __syncwarp();

    float o = 0.f;
#pragma unroll
    for (int mm = 0; mm < 32; mm++) o += sq[n][mm] * sv[mm][m];
    out[(rbase + n)*CCH + h*HDIM + m] = __float2half_rn(o);
}

// ---------------- fp16 GEMM: C[M,N] = A[M,K]*B[K,N] (+ fused epilogue) ----------------
// EPI 0: qkv  = half(acc + bias)
// EPI 1: mlp  = half(gelu(acc + bias))          (exact erf)
// EPI 2: t0[map-scattered row] += acc + bias    (window-reverse + residual, fp32)
// EPI 3: t0[row] += acc + bias                  (fp32)
// 256x64x32 tile, 256 threads = 8 warps (4 row-groups x 2 col-groups), warp = 64x32.
// 4-stage cp.async pipeline, ONE __syncthreads per K-iteration.
#define GBM 256
#define GBN 64
#define GBK 32
#define STAGES 4
#define SA_LD 40                         // halves
#define SB_LD 72                         // halves
#define SC_LD 68                         // floats
#define SA_STAGE_BYTES (GBM*SA_LD*2)     // 20480
#define SB_STAGE_BYTES (GBK*SB_LD*2)     // 4608
#define STAGE_BYTES (SA_STAGE_BYTES+SB_STAGE_BYTES)  // 25088
#define GEMM_SMEM (STAGES*STAGE_BYTES)   // 100352  (sC 256*68*4=69632 fits inside)

__device__ __forceinline__ void cp_async16(void* sptr, const void* gptr) {
    uint32_t s = (uint32_t)__cvta_generic_to_shared(sptr);
    asm volatile("cp.async.cg.shared.global [%0], [%1], 16;\n" :: "r"(s), "l"(gptr));
}

typedef wmma::fragment<wmma::matrix_a, 16,16,16, __half, wmma::row_major> FragA;
typedef wmma::fragment<wmma::matrix_b, 16,16,16, __half, wmma::row_major> FragB;
typedef wmma::fragment<wmma::accumulator, 16,16,16, float> FragC;

template<int EPI>
__global__ void __launch_bounds__(256)
gemm_f16_kernel(const __half* __restrict__ A, const __half* __restrict__ B,
                const float* __restrict__ bias, void* __restrict__ Cv,
                const int* __restrict__ map, int K, int N) {
    extern __shared__ __align__(16) char smem[];

    const int tid = threadIdx.x;
    const int bm = blockIdx.y, bn = blockIdx.x;
    const int KT = K >> 5;
    const __half* Abase = A + (size_t)bm * GBM * K;
    const __half* Bbase = B + (size_t)bn * GBN;

    const int warp = tid >> 5;
    const int wm = warp >> 1;            // 4 row-groups of 64
    const int wn = warp & 1;             // 2 col-groups of 32

    FragC acc[4][2];
#pragma unroll
    for (int i = 0; i < 4; i++)
#pragma unroll
        for (int j = 0; j < 2; j++) wmma::fill_fragment(acc[i][j], 0.f);

    auto load_tile = [&](int kt, int buf) {
        char* base = smem + buf*STAGE_BYTES;
        __half* a = (__half*)base;
#pragma unroll
        for (int i = 0; i < 4; i++) {
            int idx = tid + i*256;           // [0,1024): 256 rows x 4 chunks of 8 halves
            int r = idx >> 2, c8 = (idx & 3) << 3;
            cp_async16(a + r*SA_LD + c8, Abase + (size_t)r*K + kt*GBK + c8);
        }
        __half* b = (__half*)(base + SA_STAGE_BYTES);
        {
            int r = tid >> 3, c8 = (tid & 7) << 3;   // 32 rows x 8 chunks of 8 halves
            cp_async16(b + r*SB_LD + c8, Bbase + (size_t)(kt*GBK + r)*N + c8);
        }
        asm volatile("cp.async.commit_group;\n" ::);
    };

    // prologue: stages 0..STAGES-2  (KT >= 10 always)
#pragma unroll
    for (int s = 0; s < STAGES-1; s++) load_tile(s, s);

#pragma unroll 1
    for (int kt = 0; kt < KT; kt++) {
        // exactly kt+STAGES-1 groups committed so far -> <=2 pending means stage kt resident
        asm volatile("cp.async.wait_group 2;\n" ::);
        __syncthreads();
        int nk = kt + STAGES - 1;
        if (nk < KT) load_tile(nk, nk & (STAGES-1));
        else         asm volatile("cp.async.commit_group;\n" ::);  // keep group count in lockstep

        const char* base = smem + (kt & (STAGES-1))*STAGE_BYTES;
        const __half* a = (const __half*)base;
        const __half* b = (const __half*)(base + SA_STAGE_BYTES);
#pragma unroll
        for (int ks = 0; ks < 2; ks++) {
            FragA af[4]; FragB bf[2];
#pragma unroll
            for (int i = 0; i < 4; i++)
                wmma::load_matrix_sync(af[i], a + (wm*64 + i*16)*SA_LD + ks*16, SA_LD);
#pragma unroll
            for (int j = 0; j < 2; j++)
                wmma::load_matrix_sync(bf[j], b + (ks*16)*SB_LD + wn*32 + j*16, SB_LD);
#pragma unroll
            for (int i = 0; i < 4; i++)
#pragma unroll
                for (int j = 0; j < 2; j++)
                    wmma::mma_sync(acc[i][j], af[i], bf[j], acc[i][j]);
        }
    }

    // stage accumulators to smem fp32 (aliases pipeline buffers), then vector epilogue
    __syncthreads();
    float* sC = (float*)smem;
#pragma unroll
    for (int i = 0; i < 4; i++)
#pragma unroll
        for (int j = 0; j < 2; j++)
            wmma::store_matrix_sync(sC + (wm*64 + i*16)*SC_LD + wn*32 + j*16,
                                    acc[i][j], SC_LD, wmma::mem_row_major);
    __syncthreads();

    if (EPI == 0 || EPI == 1) {
        __half* C = (__half*)Cv;
#pragma unroll 4
        for (int idx = tid; idx < GBM*GBN/2; idx += 256) {
            int r = idx >> 5;                 // 32 half2 per row
            int c = (idx & 31) << 1;
            int col = bn*GBN + c;
            float v0 = sC[r*SC_LD + c]     + __ldg(&bias[col]);
            float v1 = sC[r*SC_LD + c + 1] + __ldg(&bias[col+1]);
            if (EPI == 1) {
                v0 = 0.5f*v0*(1.f + erff(v0*0.70710678118654752f));
                v1 = 0.5f*v1*(1.f + erff(v1*0.70710678118654752f));
            }
            size_t row = (size_t)bm*GBM + r;
            *(__half2*)&C[row*N + col] = __halves2half2(__float2half_rn(v0), __float2half_rn(v1));
        }
    } else {
        float* C = (float*)Cv;
#pragma unroll 4
        for (int idx = tid; idx < GBM*GBN/4; idx += 256) {
            int r = idx >> 4;                 // 16 float4 per row
            int c = (idx & 15) << 2;
            int col = bn*GBN + c;
            float4 v;
            v.x = sC[r*SC_LD + c]     + __ldg(&bias[col]);
            v.y = sC[r*SC_LD + c + 1] + __ldg(&bias[col+1]);
            v.z = sC[r*SC_LD + c + 2] + __ldg(&bias[col+2]);
            v.w = sC[r*SC_LD + c + 3] + __ldg(&bias[col+3]);
            size_t row = (size_t)bm*GBM + r;
            size_t drow;
            if (EPI == 2) {
                int bq = (int)(row >> 14);
                int l  = map[row & 16383];
                drow = ((size_t)bq << 14) + l;
            } else {
                drow = row;
            }
            float4* dst = (float4*)&C[drow*CCH + col];
            float4 o = *dst;
            o.x += v.x; o.y += v.y; o.z += v.z; o.w += v.w;
            *dst = o;
        }
    }
}

// ---------------- host orchestration ----------------
static void run_block(const float* const* P, const __half* wqkv, const __half* wproj,
                      const __half* wf1, const __half* wf2, int* map, int shifted,
                      float* t0, __half* xw, __half* qkv, __half* att, __half* mlp) {
    // P: ln1g ln1b qkvw qkvb bias projw projb ln2g ln2b f1w f1b f2w f2b
    ln_gather_kernel<<<TOKENS/8, 256>>>(t0, xw, P[0], P[1], map);
    gemm_f16_kernel<0><<<dim3(3*CCH/GBN, TOKENS/GBM), 256, GEMM_SMEM>>>(
        xw, wqkv, P[3], qkv, nullptr, CCH, 3*CCH);
    attn_kernel<<<BATCH*NWIN*HEADS, 1024>>>(qkv, P[4], att, shifted);
    gemm_f16_kernel<2><<<dim3(CCH/GBN, TOKENS/GBM), 256, GEMM_SMEM>>>(
        att, wproj, P[6], t0, map, CCH, CCH);
    ln_gather_kernel<<<TOKENS/8, 256>>>(t0, xw, P[7], P[8], nullptr);
    gemm_f16_kernel<1><<<dim3(4*CCH/GBN, TOKENS/GBM), 256, GEMM_SMEM>>>(
        xw, wf1, P[10], mlp, nullptr, CCH, 4*CCH);
    gemm_f16_kernel<3><<<dim3(CCH/GBN, TOKENS/GBM), 256, GEMM_SMEM>>>(
        mlp, wf2, P[12], t0, nullptr, 4*CCH, CCH);
}

extern "C" void kernel_launch(void* const* d_in, const int* in_sizes, int n_in,
                              void* d_out, int out_size) {
    (void)in_sizes; (void)n_in; (void)out_size;
    const float* x = (const float*)d_in[0];
    const float* P1[13];
    const float* P2[13];
    for (int i = 0; i < 13; i++) P1[i] = (const float*)d_in[1 + i];
    for (int i = 0; i < 13; i++) P2[i] = (const float*)d_in[14 + i];

    float *t0; __half *xw, *qkv, *att, *mlp;
    __half *wqkv, *wproj, *wf1, *wf2;
    int *map_ns, *map_s;
    cudaGetSymbolAddress((void**)&t0,  g_t0);
    cudaGetSymbolAddress((void**)&xw,  g_xw);
    cudaGetSymbolAddress((void**)&qkv, g_qkv);
    cudaGetSymbolAddress((void**)&att, g_att);
    cudaGetSymbolAddress((void**)&mlp, g_mlp);
    cudaGetSymbolAddress((void**)&wqkv, g_wqkv);
    cudaGetSymbolAddress((void**)&wproj, g_wproj);
    cudaGetSymbolAddress((void**)&wf1, g_wf1);
    cudaGetSymbolAddress((void**)&wf2, g_wf2);
    cudaGetSymbolAddress((void**)&map_ns, g_map_ns);
    cudaGetSymbolAddress((void**)&map_s,  g_map_s);

    cudaFuncSetAttribute(gemm_f16_kernel<0>, cudaFuncAttributeMaxDynamicSharedMemorySize, GEMM_SMEM);
    cudaFuncSetAttribute(gemm_f16_kernel<1>, cudaFuncAttributeMaxDynamicSharedMemorySize, GEMM_SMEM);
    cudaFuncSetAttribute(gemm_f16_kernel<2>, cudaFuncAttributeMaxDynamicSharedMemorySize, GEMM_SMEM);
    cudaFuncSetAttribute(gemm_f16_kernel<3>, cudaFuncAttributeMaxDynamicSharedMemorySize, GEMM_SMEM);

    // cast all weights to fp16 (both blocks)
    const int NW1 = CCH*3*CCH, NW2 = CCH*CCH, NW3 = CCH*4*CCH;
    for (int blk = 0; blk < 2; blk++) {
        const float* const* P = blk ? P2 : P1;
        f2h_kernel<<<(NW1+255)/256, 256>>>(P[2],  wqkv  + (size_t)blk*NW1, NW1);
        f2h_kernel<<<(NW2+255)/256, 256>>>(P[5],  wproj + (size_t)blk*NW2, NW2);
        f2h_kernel<<<(NW3+255)/256, 256>>>(P[9],  wf1   + (size_t)blk*NW3, NW3);
        f2h_kernel<<<(NW3+255)/256, 256>>>(P[11], wf2   + (size_t)blk*NW3, NW3);
    }

    init_maps_kernel<<<LL/256, 256>>>();
    transpose_in_kernel<<<dim3(LL/32, CCH/32, BATCH), dim3(32,32)>>>(x, t0);
    run_block(P1, wqkv,         wproj,         wf1,         wf2,         map_ns, 0, t0, xw, qkv, att, mlp);
    run_block(P2, wqkv + NW1,   wproj + NW2,   wf1 + NW3,   wf2 + NW3,   map_s,  1, t0, xw, qkv, att, mlp);
    transpose_out_kernel<<<dim3(LL/32, CCH/32, BATCH), dim3(32,32)>>>(t0, (float*)d_out);
}